// round 15
// baseline (speedup 1.0000x reference)
#include <cuda_runtime.h>
#include <cuda_fp16.h>
#include <cstdint>

// out[b,n] = sum_{c,hw} x[b,c,hw]*W_s[n,hw]*W_d[n,c] + W_b[n]
// GEMM Y[(b,c),n] = X[8192,3136] @ Ws[1024,3136]^T, single-fp16 mma.sync,
// fp32 accum, fused W_d epilogue, K-split 4 via atomicAdd merge.
// R14: (a) producer issues chunk i+2 BEFORE waiting full[i] (it only needs
// empty[(i+2)%3] = chunk i-1's stage, already freed) -> removes DMA-latency
// serialization on drain; (b) prep kernel 32B/thread + __ldcs streaming
// reads (27.6us @66% HBM -> ~23us).

#define K_DIM 3136
#define C_DIM 256
#define N_DIM 1024
#define M_DIM 8192
#define BM 128
#define BN 128
#define BK 64
#define KSPLIT 4
#define NCH_TOT 49            // 3136/64
#define BLK_B 16384           // one (tile,chunk) block: 128 rows * 128B
#define BLK_H 8192            // same in halves
#define STAGE_B 32768         // A + B
#define SMEM_TOTAL (1024 + 3 * STAGE_B)   // bars + 3 stages = 99328

// ---------------- scratch (alloc-free), tiled-swizzled layout ----------------
// g_X16: [64 m-tiles][49 chunks][8192 h], g_W16: [8 n-tiles][49 chunks][8192 h]
__device__ __align__(256) __half g_X16[(long)M_DIM * K_DIM];
__device__ __align__(256) __half g_W16[(long)N_DIM * K_DIM];

__device__ __forceinline__ uint32_t smem_u32(const void* p) {
    uint32_t a;
    asm("{ .reg .u64 t; cvta.to.shared.u64 t, %1; cvt.u32.u64 %0, t; }"
        : "=r"(a) : "l"(p));
    return a;
}
__device__ __forceinline__ void ldsm4(uint32_t& r0, uint32_t& r1, uint32_t& r2,
                                      uint32_t& r3, uint32_t a) {
    asm volatile("ldmatrix.sync.aligned.m8n8.x4.shared.b16 {%0,%1,%2,%3}, [%4];"
                 : "=r"(r0), "=r"(r1), "=r"(r2), "=r"(r3) : "r"(a));
}
__device__ __forceinline__ void mma16816(float* c, const uint32_t* a,
                                         const uint32_t* b) {
    asm volatile(
        "mma.sync.aligned.m16n8k16.row.col.f32.f16.f16.f32 "
        "{%0,%1,%2,%3}, {%4,%5,%6,%7}, {%8,%9}, {%0,%1,%2,%3};"
        : "+f"(c[0]), "+f"(c[1]), "+f"(c[2]), "+f"(c[3])
        : "r"(a[0]), "r"(a[1]), "r"(a[2]), "r"(a[3]), "r"(b[0]), "r"(b[1]));
}
__device__ __forceinline__ void bulk_ld(uint32_t dst, const void* src,
                                        uint32_t bytes, uint32_t mbar) {
    asm volatile(
        "cp.async.bulk.shared::cluster.global.mbarrier::complete_tx::bytes "
        "[%0], [%1], %2, [%3];"
        :: "r"(dst), "l"(src), "r"(bytes), "r"(mbar) : "memory");
}
#define MBAR_INIT(a, c) \
    asm volatile("mbarrier.init.shared.b64 [%0], %1;" :: "r"(a), "r"(c) : "memory")
#define MBAR_EXPECT(a, tx) \
    asm volatile("mbarrier.arrive.expect_tx.shared.b64 _, [%0], %1;" \
                 :: "r"(a), "r"(tx) : "memory")
#define MBAR_ARRIVE(a) \
    asm volatile("mbarrier.arrive.shared.b64 _, [%0];" :: "r"(a) : "memory")
__device__ __forceinline__ void mbar_wait(uint32_t mbar, uint32_t parity) {
    asm volatile(
        "{ .reg .pred P1;\n"
        "WL_%=:\n"
        "mbarrier.try_wait.parity.acquire.cta.shared::cta.b64 P1, [%0], %1, 0x989680;\n"
        "@P1 bra.uni WD_%=;\n"
        "bra.uni WL_%=;\n"
        "WD_%=: }"
        :: "r"(mbar), "r"(parity) : "memory");
}

// ---------------- prep: fp32 -> fp16 tiled-swizzled + bias (32B/thread) -----
__global__ void prep_kernel(const float* __restrict__ x,
                            const float* __restrict__ ws,
                            const float* __restrict__ wb,
                            float* __restrict__ out) {
    const long NXC = 64L * NCH_TOT * 512;    // X: 32B-unit count
    const long NWC = 8L * NCH_TOT * 512;     // W: 32B-unit count
    long i = (long)blockIdx.x * blockDim.x + threadIdx.x;
    if (i < NXC + NWC) {
        const bool isX = i < NXC;
        const long j = isX ? i : i - NXC;
        const int c2 = (int)(j & 3);         // 32B pair within row (chunks 2c2,2c2+1)
        const int row = (int)((j >> 2) & 127);
        const int ch = (int)((j >> 9) % NCH_TOT);
        const int tile = (int)(j / (512L * NCH_TOT));
        const float* src = (isX ? x : ws) +
            ((long)(tile * BM + row) * K_DIM + (long)ch * BK + c2 * 16);
        float4 v0 = __ldcs((const float4*)src);
        float4 v1 = __ldcs((const float4*)src + 1);
        float4 v2 = __ldcs((const float4*)src + 2);
        float4 v3 = __ldcs((const float4*)src + 3);
        __half2 h0 = __floats2half2_rn(v0.x, v0.y);
        __half2 h1 = __floats2half2_rn(v0.z, v0.w);
        __half2 h2 = __floats2half2_rn(v1.x, v1.y);
        __half2 h3 = __floats2half2_rn(v1.z, v1.w);
        __half2 h4 = __floats2half2_rn(v2.x, v2.y);
        __half2 h5 = __floats2half2_rn(v2.z, v2.w);
        __half2 h6 = __floats2half2_rn(v3.x, v3.y);
        __half2 h7 = __floats2half2_rn(v3.z, v3.w);
        uint4 r0, r1;
        r0.x = *(const uint32_t*)&h0; r0.y = *(const uint32_t*)&h1;
        r0.z = *(const uint32_t*)&h2; r0.w = *(const uint32_t*)&h3;
        r1.x = *(const uint32_t*)&h4; r1.y = *(const uint32_t*)&h5;
        r1.z = *(const uint32_t*)&h6; r1.w = *(const uint32_t*)&h7;
        __half* base = isX ? g_X16 : g_W16;
        char* blk = (char*)(base + ((long)tile * NCH_TOT + ch) * BLK_H) +
                    row * 128;
        const int k = row & 7;
        *(uint4*)(blk + ((((2 * c2)     ^ k)) << 4)) = r0;
        *(uint4*)(blk + ((((2 * c2 + 1) ^ k)) << 4)) = r1;
    } else if (i < NXC + NWC + 4096) {       // bias: 8 floats per thread
        long j = (i - NXC - NWC) * 8;        // 0..32767
        int nb = (int)(j & (N_DIM - 1));
        float4 b0 = *(const float4*)(wb + nb);
        float4 b1 = *(const float4*)(wb + nb + 4);
        *(float4*)(out + j) = b0;
        *(float4*)(out + j + 4) = b1;
    }
}

// ---------------- main GEMM ----------------
// barriers: full[s] at sb+8s (count 1, tx), empty[s] at sb+24+8s (count 8).
__global__ __launch_bounds__(256, 2)
void gemm_kernel(const float* __restrict__ Wd, float* __restrict__ out) {
    extern __shared__ char smem[];
    const uint32_t sb = smem_u32(smem);
    const uint32_t stage0 = sb + 1024u;
    const int tid = threadIdx.x;
    const int lane = tid & 31;
    const int warp = tid >> 5;
    const int mt = blockIdx.y;
    const int nt = blockIdx.x;
    const int m0 = mt * BM;
    const int n0 = nt * BN;
    const int mwarp = (warp >> 2) * 64;   // 2 warp-rows
    const int nwarp = (warp & 3) * 32;    // 4 warp-cols

    // K-split range: boundaries 0,13,25,37,49
    const int z = blockIdx.z;
    const int cs = (z == 0) ? 0 : 13 + 12 * (z - 1);
    const int nch = 13 + 12 * z - cs;

    float acc[4][4][4];
#pragma unroll
    for (int i = 0; i < 4; ++i)
#pragma unroll
        for (int j = 0; j < 4; ++j)
#pragma unroll
            for (int k = 0; k < 4; ++k) acc[i][j][k] = 0.f;

    const uint32_t e = (uint32_t)(lane & 7);          // swizzle key
    const uint32_t a_row = (uint32_t)(mwarp + (lane & 15)) * 128u;
    const uint32_t b_row =
        (uint32_t)(nwarp + (lane & 7) + ((lane >> 4) & 1) * 8) * 128u;
    uint32_t akoff[4], bkoff[4];
#pragma unroll
    for (int ks = 0; ks < 4; ++ks) {
        akoff[ks] = (((uint32_t)(ks * 2 + (lane >> 4)) ^ e) << 4);
        bkoff[ks] = (((uint32_t)(ks * 2 + ((lane >> 3) & 1)) ^ e) << 4);
    }

    // producer: tid0 waits empty, then expect_tx + two 16KB bulk copies
    const __half* srcA = g_X16 + ((long)mt * NCH_TOT + cs) * BLK_H;
    const __half* srcB = g_W16 + ((long)nt * NCH_TOT + cs) * BLK_H;
    auto issue = [&](int j) {   // local chunk j
        const uint32_t s = (uint32_t)(j % 3);
        mbar_wait(sb + 24u + 8u * s, (uint32_t)((j / 3 + 1) & 1));
        const uint32_t mb = sb + 8u * s;
        const uint32_t st = stage0 + s * STAGE_B;
        MBAR_EXPECT(mb, (uint32_t)STAGE_B);
        bulk_ld(st, srcA + (long)j * BLK_H, BLK_B, mb);
        bulk_ld(st + BLK_B, srcB + (long)j * BLK_H, BLK_B, mb);
    };

    if (tid == 0) {
        MBAR_INIT(sb + 0, 1);    // full[0..2]
        MBAR_INIT(sb + 8, 1);
        MBAR_INIT(sb + 16, 1);
        MBAR_INIT(sb + 24, 8);   // empty[0..2]: one arrive per warp
        MBAR_INIT(sb + 32, 8);
        MBAR_INIT(sb + 40, 8);
    }
    __syncthreads();
    if (tid == 0) { issue(0); issue(1); }

    for (int i = 0; i < nch; ++i) {
        const uint32_t s = (uint32_t)(i % 3);
        // issue i+2 FIRST: it only needs empty[(i+2)%3] (chunk i-1's stage),
        // not chunk i's data -> DMA starts before the full-wait below.
        if (tid == 0 && i + 2 < nch) issue(i + 2);
        mbar_wait(sb + 8u * s, (uint32_t)((i / 3) & 1));   // full[s]

        const uint32_t st = stage0 + s * STAGE_B;
        const uint32_t Ab = st + a_row;
        const uint32_t Bb = st + BLK_B + b_row;
#pragma unroll
        for (int ks = 0; ks < 4; ++ks) {
            uint32_t a[4][4], b[4][2];
#pragma unroll
            for (int mi = 0; mi < 4; ++mi)
                ldsm4(a[mi][0], a[mi][1], a[mi][2], a[mi][3],
                      Ab + (uint32_t)(mi * 16 * 128) + akoff[ks]);
#pragma unroll
            for (int seg = 0; seg < 2; ++seg)
                ldsm4(b[2 * seg][0], b[2 * seg][1], b[2 * seg + 1][0],
                      b[2 * seg + 1][1],
                      Bb + (uint32_t)(seg * 16 * 128) + bkoff[ks]);
            if (ks == 3 && lane == 0)
                MBAR_ARRIVE(sb + 24u + 8u * s);  // stage free: regs hold data
#pragma unroll
            for (int mi = 0; mi < 4; ++mi)
#pragma unroll
                for (int ni = 0; ni < 4; ++ni)
                    mma16816(acc[mi][ni], a[mi], b[ni]);
        }
    }

    // ---------------- fused epilogue (partial over this z's K range) --------
    const int b = m0 >> 8;
    const int cbase = (m0 & (C_DIM - 1)) + mwarp;
    const int g = lane >> 2;
    const int t = lane & 3;

    float p[4][2];
#pragma unroll
    for (int ni = 0; ni < 4; ++ni) { p[ni][0] = 0.f; p[ni][1] = 0.f; }

#pragma unroll
    for (int mi = 0; mi < 4; ++mi) {
        const int c0 = cbase + mi * 16 + g;
#pragma unroll
        for (int ni = 0; ni < 4; ++ni) {
            const int n = n0 + nwarp + ni * 8 + 2 * t;
#pragma unroll
            for (int j = 0; j < 2; ++j) {
                const float w0 = __ldg(Wd + (long)(n + j) * C_DIM + c0);
                const float w1 = __ldg(Wd + (long)(n + j) * C_DIM + c0 + 8);
                p[ni][j] += acc[mi][ni][j] * w0 + acc[mi][ni][j + 2] * w1;
            }
        }
    }
#pragma unroll
    for (int ni = 0; ni < 4; ++ni)
#pragma unroll
        for (int j = 0; j < 2; ++j) {
#pragma unroll
            for (int mk = 4; mk <= 16; mk <<= 1)
                p[ni][j] += __shfl_xor_sync(0xFFFFFFFFu, p[ni][j], mk);
        }
    if (lane < 4) {
#pragma unroll
        for (int ni = 0; ni < 4; ++ni)
#pragma unroll
            for (int j = 0; j < 2; ++j)
                atomicAdd(out + (long)b * N_DIM + n0 + nwarp + ni * 8 + 2 * t + j,
                          p[ni][j]);
    }
}

extern "C" void kernel_launch(void* const* d_in, const int* in_sizes, int n_in,
                              void* d_out, int out_size) {
    const float* x  = (const float*)d_in[0];  // (32,256,56,56)
    const float* Ws = (const float*)d_in[1];  // (1024,56,56)
    const float* Wd = (const float*)d_in[2];  // (1024,256,1,1)
    const float* Wb = (const float*)d_in[3];  // (1,1024)
    float* out = (float*)d_out;               // (32,1024)

    cudaFuncSetAttribute(gemm_kernel,
                         cudaFuncAttributeMaxDynamicSharedMemorySize, SMEM_TOTAL);

    const long nthreads = 64L * NCH_TOT * 512 + 8L * NCH_TOT * 512 + 4096;
    prep_kernel<<<(int)((nthreads + 255) / 256), 256>>>(x, Ws, Wb, out);

    dim3 grid(N_DIM / BN, M_DIM / BM, KSPLIT);  // (8, 64, 4)
    gemm_kernel<<<grid, 256, SMEM_TOTAL>>>(Wd, out);
}

// round 16
// speedup vs baseline: 1.0459x; 1.0459x over previous
#include <cuda_runtime.h>
#include <cuda_fp16.h>
#include <cstdint>

// out[b,n] = sum_{c,hw} x[b,c,hw]*W_s[n,hw]*W_d[n,c] + W_b[n]
// GEMM Y[(b,c),n] = X[8192,3136] @ Ws[1024,3136]^T, single-fp16 mma.sync,
// fp32 accum, fused W_d epilogue, K-split 4 via atomicAdd merge.
// R15: 64x64 warp tiles (4 warps, 128 thr, 2 CTAs/SM, ~180 regs/thread).
// LDSM bytes/HMMA drop 384->256 (R14 ledger: L1 wavefronts >= tensor cycles
// was the co-bound; this puts L1 at ~79% of tensor so tensor can run free).

#define K_DIM 3136
#define C_DIM 256
#define N_DIM 1024
#define M_DIM 8192
#define BM 128
#define BN 128
#define BK 64
#define KSPLIT 4
#define NCH_TOT 49            // 3136/64
#define BLK_B 16384           // one (tile,chunk) block: 128 rows * 128B
#define BLK_H 8192            // same in halves
#define STAGE_B 32768         // A + B
#define SMEM_TOTAL (1024 + 3 * STAGE_B)   // bars + 3 stages = 99328

// ---------------- scratch (alloc-free), tiled-swizzled layout ----------------
// g_X16: [64 m-tiles][49 chunks][8192 h], g_W16: [8 n-tiles][49 chunks][8192 h]
__device__ __align__(256) __half g_X16[(long)M_DIM * K_DIM];
__device__ __align__(256) __half g_W16[(long)N_DIM * K_DIM];

__device__ __forceinline__ uint32_t smem_u32(const void* p) {
    uint32_t a;
    asm("{ .reg .u64 t; cvta.to.shared.u64 t, %1; cvt.u32.u64 %0, t; }"
        : "=r"(a) : "l"(p));
    return a;
}
__device__ __forceinline__ void ldsm4(uint32_t& r0, uint32_t& r1, uint32_t& r2,
                                      uint32_t& r3, uint32_t a) {
    asm volatile("ldmatrix.sync.aligned.m8n8.x4.shared.b16 {%0,%1,%2,%3}, [%4];"
                 : "=r"(r0), "=r"(r1), "=r"(r2), "=r"(r3) : "r"(a));
}
__device__ __forceinline__ void mma16816(float* c, const uint32_t* a,
                                         const uint32_t* b) {
    asm volatile(
        "mma.sync.aligned.m16n8k16.row.col.f32.f16.f16.f32 "
        "{%0,%1,%2,%3}, {%4,%5,%6,%7}, {%8,%9}, {%0,%1,%2,%3};"
        : "+f"(c[0]), "+f"(c[1]), "+f"(c[2]), "+f"(c[3])
        : "r"(a[0]), "r"(a[1]), "r"(a[2]), "r"(a[3]), "r"(b[0]), "r"(b[1]));
}
__device__ __forceinline__ void bulk_ld(uint32_t dst, const void* src,
                                        uint32_t bytes, uint32_t mbar) {
    asm volatile(
        "cp.async.bulk.shared::cluster.global.mbarrier::complete_tx::bytes "
        "[%0], [%1], %2, [%3];"
        :: "r"(dst), "l"(src), "r"(bytes), "r"(mbar) : "memory");
}
#define MBAR_INIT(a, c) \
    asm volatile("mbarrier.init.shared.b64 [%0], %1;" :: "r"(a), "r"(c) : "memory")
#define MBAR_EXPECT(a, tx) \
    asm volatile("mbarrier.arrive.expect_tx.shared.b64 _, [%0], %1;" \
                 :: "r"(a), "r"(tx) : "memory")
#define MBAR_ARRIVE(a) \
    asm volatile("mbarrier.arrive.shared.b64 _, [%0];" :: "r"(a) : "memory")
__device__ __forceinline__ void mbar_wait(uint32_t mbar, uint32_t parity) {
    asm volatile(
        "{ .reg .pred P1;\n"
        "WL_%=:\n"
        "mbarrier.try_wait.parity.acquire.cta.shared::cta.b64 P1, [%0], %1, 0x989680;\n"
        "@P1 bra.uni WD_%=;\n"
        "bra.uni WL_%=;\n"
        "WD_%=: }"
        :: "r"(mbar), "r"(parity) : "memory");
}

// ---------------- prep: fp32 -> fp16 tiled-swizzled + bias ------------------
__global__ void prep_kernel(const float* __restrict__ x,
                            const float* __restrict__ ws,
                            const float* __restrict__ wb,
                            float* __restrict__ out) {
    const long NXC = 64L * NCH_TOT * 1024;   // X: 16B-chunk count
    const long NWC = 8L * NCH_TOT * 1024;    // W: 16B-chunk count
    long i = (long)blockIdx.x * blockDim.x + threadIdx.x;
    if (i < NXC + NWC) {
        const bool isX = i < NXC;
        const long j = isX ? i : i - NXC;
        const int c = (int)(j & 7);          // 16B col within row
        const int row = (int)((j >> 3) & 127);
        const int ch = (int)((j >> 10) % NCH_TOT);
        const int tile = (int)(j / (1024L * NCH_TOT));
        const float* src = (isX ? x : ws) +
            ((long)(tile * BM + row) * K_DIM + (long)ch * BK + c * 8);
        float4 v0 = __ldcs((const float4*)src);
        float4 v1 = __ldcs((const float4*)src + 1);
        __half2 h0 = __floats2half2_rn(v0.x, v0.y);
        __half2 h1 = __floats2half2_rn(v0.z, v0.w);
        __half2 h2 = __floats2half2_rn(v1.x, v1.y);
        __half2 h3 = __floats2half2_rn(v1.z, v1.w);
        uint4 r;
        r.x = *(const uint32_t*)&h0; r.y = *(const uint32_t*)&h1;
        r.z = *(const uint32_t*)&h2; r.w = *(const uint32_t*)&h3;
        __half* base = isX ? g_X16 : g_W16;
        const long blk = ((long)tile * NCH_TOT + ch) * BLK_H;
        const uint32_t soff =
            (uint32_t)(row * 128) + (((uint32_t)(c ^ (row & 7))) << 4);
        *(uint4*)((char*)(base + blk) + soff) = r;
    } else if (i < NXC + NWC + 4096) {       // bias: 8 floats per thread
        long j = (i - NXC - NWC) * 8;        // 0..32767
        int nb = (int)(j & (N_DIM - 1));
        float4 b0 = *(const float4*)(wb + nb);
        float4 b1 = *(const float4*)(wb + nb + 4);
        *(float4*)(out + j) = b0;
        *(float4*)(out + j + 4) = b1;
    }
}

// ---------------- main GEMM ----------------
// barriers: full[s] at sb+8s (count 1, tx), empty[s] at sb+24+8s (count 4).
__global__ __launch_bounds__(128, 2)
void gemm_kernel(const float* __restrict__ Wd, float* __restrict__ out) {
    extern __shared__ char smem[];
    const uint32_t sb = smem_u32(smem);
    const uint32_t stage0 = sb + 1024u;
    const int tid = threadIdx.x;
    const int lane = tid & 31;
    const int warp = tid >> 5;            // 0..3
    const int mt = blockIdx.y;
    const int nt = blockIdx.x;
    const int m0 = mt * BM;
    const int n0 = nt * BN;
    const int mwarp = (warp >> 1) * 64;   // 2 warp-rows
    const int nwarp = (warp & 1) * 64;    // 2 warp-cols, 64 wide

    // K-split range: boundaries 0,13,25,37,49
    const int z = blockIdx.z;
    const int cs = (z == 0) ? 0 : 13 + 12 * (z - 1);
    const int nch = 13 + 12 * z - cs;

    float acc[4][8][4];
#pragma unroll
    for (int i = 0; i < 4; ++i)
#pragma unroll
        for (int j = 0; j < 8; ++j)
#pragma unroll
            for (int k = 0; k < 4; ++k) acc[i][j][k] = 0.f;

    const uint32_t e = (uint32_t)(lane & 7);          // swizzle key
    const uint32_t a_row = (uint32_t)(mwarp + (lane & 15)) * 128u;
    const uint32_t b_row =
        (uint32_t)(nwarp + (lane & 7) + ((lane >> 4) & 1) * 8) * 128u;
    uint32_t akoff[4], bkoff[4];
#pragma unroll
    for (int ks = 0; ks < 4; ++ks) {
        akoff[ks] = (((uint32_t)(ks * 2 + (lane >> 4)) ^ e) << 4);
        bkoff[ks] = (((uint32_t)(ks * 2 + ((lane >> 3) & 1)) ^ e) << 4);
    }

    // producer: tid0 waits empty, then expect_tx + two 16KB bulk copies
    const __half* srcA = g_X16 + ((long)mt * NCH_TOT + cs) * BLK_H;
    const __half* srcB = g_W16 + ((long)nt * NCH_TOT + cs) * BLK_H;
    auto issue = [&](int j) {   // local chunk j
        const uint32_t s = (uint32_t)(j % 3);
        mbar_wait(sb + 24u + 8u * s, (uint32_t)((j / 3 + 1) & 1));
        const uint32_t mb = sb + 8u * s;
        const uint32_t st = stage0 + s * STAGE_B;
        MBAR_EXPECT(mb, (uint32_t)STAGE_B);
        bulk_ld(st, srcA + (long)j * BLK_H, BLK_B, mb);
        bulk_ld(st + BLK_B, srcB + (long)j * BLK_H, BLK_B, mb);
    };

    if (tid == 0) {
        MBAR_INIT(sb + 0, 1);    // full[0..2]
        MBAR_INIT(sb + 8, 1);
        MBAR_INIT(sb + 16, 1);
        MBAR_INIT(sb + 24, 4);   // empty[0..2]: one arrive per warp
        MBAR_INIT(sb + 32, 4);
        MBAR_INIT(sb + 40, 4);
    }
    __syncthreads();
    if (tid == 0) { issue(0); issue(1); }

    for (int i = 0; i < nch; ++i) {
        const uint32_t s = (uint32_t)(i % 3);
        if (tid == 0 && i + 2 < nch) issue(i + 2);
        mbar_wait(sb + 8u * s, (uint32_t)((i / 3) & 1));   // full[s]

        const uint32_t st = stage0 + s * STAGE_B;
        const uint32_t Ab = st + a_row;
        const uint32_t Bb = st + BLK_B + b_row;
#pragma unroll
        for (int ks = 0; ks < 4; ++ks) {
            uint32_t a[4][4], b[8][2];
#pragma unroll
            for (int mi = 0; mi < 4; ++mi)
                ldsm4(a[mi][0], a[mi][1], a[mi][2], a[mi][3],
                      Ab + (uint32_t)(mi * 16 * 128) + akoff[ks]);
#pragma unroll
            for (int seg = 0; seg < 4; ++seg)
                ldsm4(b[2 * seg][0], b[2 * seg][1], b[2 * seg + 1][0],
                      b[2 * seg + 1][1],
                      Bb + (uint32_t)(seg * 16 * 128) + bkoff[ks]);
            if (ks == 3 && lane == 0)
                MBAR_ARRIVE(sb + 24u + 8u * s);  // stage free: regs hold data
#pragma unroll
            for (int mi = 0; mi < 4; ++mi)
#pragma unroll
                for (int ni = 0; ni < 8; ++ni)
                    mma16816(acc[mi][ni], a[mi], b[ni]);
        }
    }

    // ---------------- fused epilogue (partial over this z's K range) --------
    const int b = m0 >> 8;
    const int cbase = (m0 & (C_DIM - 1)) + mwarp;
    const int g = lane >> 2;
    const int t = lane & 3;

    float p[8][2];
#pragma unroll
    for (int ni = 0; ni < 8; ++ni) { p[ni][0] = 0.f; p[ni][1] = 0.f; }

#pragma unroll
    for (int mi = 0; mi < 4; ++mi) {
        const int c0 = cbase + mi * 16 + g;
#pragma unroll
        for (int ni = 0; ni < 8; ++ni) {
            const int n = n0 + nwarp + ni * 8 + 2 * t;
#pragma unroll
            for (int j = 0; j < 2; ++j) {
                const float w0 = __ldg(Wd + (long)(n + j) * C_DIM + c0);
                const float w1 = __ldg(Wd + (long)(n + j) * C_DIM + c0 + 8);
                p[ni][j] += acc[mi][ni][j] * w0 + acc[mi][ni][j + 2] * w1;
            }
        }
    }
#pragma unroll
    for (int ni = 0; ni < 8; ++ni)
#pragma unroll
        for (int j = 0; j < 2; ++j) {
#pragma unroll
            for (int mk = 4; mk <= 16; mk <<= 1)
                p[ni][j] += __shfl_xor_sync(0xFFFFFFFFu, p[ni][j], mk);
        }
    if (lane < 4) {
#pragma unroll
        for (int ni = 0; ni < 8; ++ni)
#pragma unroll
            for (int j = 0; j < 2; ++j)
                atomicAdd(out + (long)b * N_DIM + n0 + nwarp + ni * 8 + 2 * t + j,
                          p[ni][j]);
    }
}

extern "C" void kernel_launch(void* const* d_in, const int* in_sizes, int n_in,
                              void* d_out, int out_size) {
    const float* x  = (const float*)d_in[0];  // (32,256,56,56)
    const float* Ws = (const float*)d_in[1];  // (1024,56,56)
    const float* Wd = (const float*)d_in[2];  // (1024,256,1,1)
    const float* Wb = (const float*)d_in[3];  // (1,1024)
    float* out = (float*)d_out;               // (32,1024)

    cudaFuncSetAttribute(gemm_kernel,
                         cudaFuncAttributeMaxDynamicSharedMemorySize, SMEM_TOTAL);

    const long nthreads = 64L * NCH_TOT * 1024 + 8L * NCH_TOT * 1024 + 4096;
    prep_kernel<<<(int)((nthreads + 255) / 256), 256>>>(x, Ws, Wb, out);

    dim3 grid(N_DIM / BN, M_DIM / BM, KSPLIT);  // (8, 64, 4)
    gemm_kernel<<<grid, 128, SMEM_TOTAL>>>(Wd, out);
}